// round 2
// baseline (speedup 1.0000x reference)
#include <cuda_runtime.h>
#include <cstdint>

#define S_LEN 2048
#define HDIM  64
#define NH    16
#define BSZ   2
#define BH    32          // BSZ*NH
#define DM    1024
#define RK    16
#define F_EPS 1e-6f
#define CLIPA 10.0f

// ---------------- scratch (device globals; no allocation allowed) ----------------
__device__ float g_q[4194304];       // [B,H,S,Dh]
__device__ float g_k[4194304];
__device__ float g_v[4194304];
__device__ float g_kmat[134217728];  // masked kernel [B,H,S,S], diag = 0 (512 MiB)
__device__ float g_qsq[65536];       // [B,H,S]
__device__ float g_ksq[65536];
__device__ float g_lr[524288];       // [H,S,RK]
__device__ float g_alpha[4194304];   // [B,H,S,Dh]
__device__ float g_resid[4194304];
__device__ float g_ltr[262144];      // [BH, 8 partials, RK, Dh]
__device__ float g_ctx[4194304];     // [B,S,H*Dh]

__device__ __forceinline__ float softplusf(float x) {
    return (x > 20.f) ? x : log1pf(__expf(x));
}

// ---------------- generic NT SGEMM: C[m,n] = sum_k A[m,k]*B[n,k] ----------------
// BM=128, BN=128, BK=16, 256 threads, 8x8 micro-tile.
// mode 0: C row-major [M,N].  mode 1: scatter to [B,H,S,Dh] (QKV projection).
__global__ __launch_bounds__(256) void gemm_nt_kernel(
    const float* __restrict__ A, const float* __restrict__ B,
    float* __restrict__ C, int M, int N, int K, int mode)
{
    __shared__ float As[16][128];
    __shared__ float Bs[16][128];
    const int tid = threadIdx.x;
    const int m0 = blockIdx.y * 128;
    const int n0 = blockIdx.x * 128;
    const int tm = tid >> 4, tn = tid & 15;
    const int lr_ = tid >> 2;          // 0..63
    const int lc  = (tid & 3) * 4;     // 0,4,8,12
    const float* Ag = A + (size_t)(m0 + lr_) * K + lc;
    const float* Bg = B + (size_t)(n0 + lr_) * K + lc;

    float acc[8][8];
#pragma unroll
    for (int i = 0; i < 8; i++)
#pragma unroll
        for (int j = 0; j < 8; j++) acc[i][j] = 0.f;

    for (int kk = 0; kk < K; kk += 16) {
        float4 a0 = *(const float4*)(Ag + kk);
        float4 a1 = *(const float4*)(Ag + (size_t)64 * K + kk);
        float4 b0 = *(const float4*)(Bg + kk);
        float4 b1 = *(const float4*)(Bg + (size_t)64 * K + kk);
        As[lc+0][lr_]    = a0.x; As[lc+1][lr_]    = a0.y; As[lc+2][lr_]    = a0.z; As[lc+3][lr_]    = a0.w;
        As[lc+0][lr_+64] = a1.x; As[lc+1][lr_+64] = a1.y; As[lc+2][lr_+64] = a1.z; As[lc+3][lr_+64] = a1.w;
        Bs[lc+0][lr_]    = b0.x; Bs[lc+1][lr_]    = b0.y; Bs[lc+2][lr_]    = b0.z; Bs[lc+3][lr_]    = b0.w;
        Bs[lc+0][lr_+64] = b1.x; Bs[lc+1][lr_+64] = b1.y; Bs[lc+2][lr_+64] = b1.z; Bs[lc+3][lr_+64] = b1.w;
        __syncthreads();
#pragma unroll
        for (int k = 0; k < 16; k++) {
            float a[8], b[8];
            *(float4*)&a[0] = *(const float4*)&As[k][tm*8];
            *(float4*)&a[4] = *(const float4*)&As[k][tm*8+4];
            *(float4*)&b[0] = *(const float4*)&Bs[k][tn*8];
            *(float4*)&b[4] = *(const float4*)&Bs[k][tn*8+4];
#pragma unroll
            for (int i = 0; i < 8; i++)
#pragma unroll
                for (int j = 0; j < 8; j++) acc[i][j] = fmaf(a[i], b[j], acc[i][j]);
        }
        __syncthreads();
    }

    if (mode == 0) {
#pragma unroll
        for (int i = 0; i < 8; i++) {
            int row = m0 + tm*8 + i;
            float4 o0 = make_float4(acc[i][0], acc[i][1], acc[i][2], acc[i][3]);
            float4 o1 = make_float4(acc[i][4], acc[i][5], acc[i][6], acc[i][7]);
            *(float4*)&C[(size_t)row * N + n0 + tn*8]     = o0;
            *(float4*)&C[(size_t)row * N + n0 + tn*8 + 4] = o1;
        }
    } else {
        // row = b*S+s ; col = h*64+d ; dest [b][h][s][d]
#pragma unroll
        for (int i = 0; i < 8; i++) {
            int row = m0 + tm*8 + i;
            int b = row >> 11, s = row & (S_LEN - 1);
            int col = n0 + tn*8;           // 8-aligned, stays within one head
            int h = col >> 6, d = col & 63;
            float* dst = &C[(((size_t)(b*NH + h)) * S_LEN + s) * HDIM + d];
            float4 o0 = make_float4(acc[i][0], acc[i][1], acc[i][2], acc[i][3]);
            float4 o1 = make_float4(acc[i][4], acc[i][5], acc[i][6], acc[i][7]);
            *(float4*)dst       = o0;
            *(float4*)(dst + 4) = o1;
        }
    }
}

// ---------------- per-row squared norms of q and k ----------------
__global__ void rowsq_kernel() {
    int g = blockIdx.x * blockDim.x + threadIdx.x;
    int warp = g >> 5, lane = g & 31;
    const float* src; float* dst; int row;
    if (warp < BH * S_LEN) { src = g_q; dst = g_qsq; row = warp; }
    else                   { src = g_k; dst = g_ksq; row = warp - BH * S_LEN; }
    float a = src[(size_t)row * HDIM + lane];
    float b = src[(size_t)row * HDIM + lane + 32];
    float s = a*a + b*b;
#pragma unroll
    for (int off = 16; off; off >>= 1) s += __shfl_xor_sync(0xffffffffu, s, off);
    if (lane == 0) dst[row] = s;
}

// ---------------- masked kernel build: exp RBF, diag = 0 (exact) ----------------
// per bh: C[s,t] = exp(-max(qs+kt-2 q.k,0)/(2 bw^2)), C[s,s]=0. M=2048(BM128) N=2048(BN64) K=64
__global__ __launch_bounds__(256) void build_kernel(const float* __restrict__ bandwidth)
{
    __shared__ float Qs[64][128];   // [k][m]
    __shared__ float Ks[64][64];    // [k][n]
    int tid = threadIdx.x;
    int bh = blockIdx.z;
    int m0 = blockIdx.y * 128;
    int n0 = blockIdx.x * 64;
    size_t base = (size_t)bh * S_LEN * HDIM;

#pragma unroll
    for (int i = 0; i < 8; i++) {
        int f4 = tid + i * 256;
        int row = f4 >> 4, c4 = (f4 & 15) * 4;
        float4 v = *(const float4*)&g_q[base + (size_t)(m0 + row) * HDIM + c4];
        Qs[c4+0][row] = v.x; Qs[c4+1][row] = v.y; Qs[c4+2][row] = v.z; Qs[c4+3][row] = v.w;
    }
#pragma unroll
    for (int i = 0; i < 4; i++) {
        int f4 = tid + i * 256;
        int row = f4 >> 4, c4 = (f4 & 15) * 4;
        float4 v = *(const float4*)&g_k[base + (size_t)(n0 + row) * HDIM + c4];
        Ks[c4+0][row] = v.x; Ks[c4+1][row] = v.y; Ks[c4+2][row] = v.z; Ks[c4+3][row] = v.w;
    }
    __syncthreads();

    int tm = tid >> 4, tn = tid & 15;
    float acc[8][4];
#pragma unroll
    for (int i = 0; i < 8; i++)
#pragma unroll
        for (int j = 0; j < 4; j++) acc[i][j] = 0.f;

#pragma unroll 16
    for (int k = 0; k < 64; k++) {
        float a[8], b[4];
        *(float4*)&a[0] = *(const float4*)&Qs[k][tm*8];
        *(float4*)&a[4] = *(const float4*)&Qs[k][tm*8+4];
        *(float4*)&b[0] = *(const float4*)&Ks[k][tn*4];
#pragma unroll
        for (int i = 0; i < 8; i++)
#pragma unroll
            for (int j = 0; j < 4; j++) acc[i][j] = fmaf(a[i], b[j], acc[i][j]);
    }

    float bw = softplusf(bandwidth[0]) + F_EPS;
    float inv2 = 1.f / (2.f * bw * bw);
    int sbase = bh * S_LEN;
    int gcol = n0 + tn * 4;
    float4 ks4 = *(const float4*)&g_ksq[sbase + gcol];
#pragma unroll
    for (int i = 0; i < 8; i++) {
        int grow = m0 + tm*8 + i;
        float qs = g_qsq[sbase + grow];
        float4 o;
        float d0 = fmaxf(qs + ks4.x - 2.f*acc[i][0], 0.f); o.x = __expf(-d0 * inv2);
        float d1 = fmaxf(qs + ks4.y - 2.f*acc[i][1], 0.f); o.y = __expf(-d1 * inv2);
        float d2 = fmaxf(qs + ks4.z - 2.f*acc[i][2], 0.f); o.z = __expf(-d2 * inv2);
        float d3 = fmaxf(qs + ks4.w - 2.f*acc[i][3], 0.f); o.w = __expf(-d3 * inv2);
        if (grow == gcol    ) o.x = 0.f;   // exact zero diagonal (masked kernel)
        if (grow == gcol + 1) o.y = 0.f;
        if (grow == gcol + 2) o.z = 0.f;
        if (grow == gcol + 3) o.w = 0.f;
        *(float4*)&g_kmat[((size_t)bh * S_LEN + grow) * S_LEN + gcol] = o;
    }
}

// ---------------- lr[h,s,t] = sum_r pos[s,r] * proj[h,r,t] ----------------
__global__ void lr_kernel(const float* __restrict__ pos, const float* __restrict__ proj) {
    int idx = blockIdx.x * blockDim.x + threadIdx.x;   // H*S
    int h = idx >> 11, s = idx & (S_LEN - 1);
    float p[16];
#pragma unroll
    for (int i = 0; i < 4; i++) *(float4*)&p[i*4] = *(const float4*)&pos[(size_t)s * RK + i*4];
    const float* pr = proj + (size_t)h * RK * RK;
    float out[16];
#pragma unroll
    for (int t = 0; t < 16; t++) {
        float sum = 0.f;
#pragma unroll
        for (int r = 0; r < 16; r++) sum = fmaf(p[r], pr[r*16 + t], sum);
        out[t] = sum;
    }
#pragma unroll
    for (int i = 0; i < 4; i++)
        *(float4*)&g_lr[((size_t)h * S_LEN + s) * RK + i*4] = *(float4*)&out[i*4];
}

// ---------------- solve GEMM: acc = K_masked[bh] @ Bop[bh]  (M2048 N64 K2048) ----------------
// epi 0: g_resid = v - acc - lam*alpha      (residual against K_reg = K + lam*I)
// epi 1: out = acc (diag contributes exactly 0) ; XSA subtract ; write g_ctx [B,S,H*Dh]
__global__ __launch_bounds__(256) void solve_gemm_kernel(
    const float* __restrict__ Bop, int epi,
    const float* __restrict__ lambda_reg, const float* __restrict__ xsa_scale)
{
    __shared__ float As[16][128];
    __shared__ float Bs[16][64];
    int tid = threadIdx.x;
    int bh = blockIdx.y;
    int m0 = blockIdx.x * 128;
    const float* A  = g_kmat + (size_t)bh * S_LEN * S_LEN;
    const float* Bg = Bop    + (size_t)bh * S_LEN * HDIM;
    int tm = tid >> 4, tn = tid & 15;
    int ar0 = tid >> 2;            // 0..63
    int ac  = (tid & 3) * 4;
    int br  = tid >> 4;            // 0..15
    int bc  = (tid & 15) * 4;

    float acc[8][4];
#pragma unroll
    for (int i = 0; i < 8; i++)
#pragma unroll
        for (int j = 0; j < 4; j++) acc[i][j] = 0.f;

    for (int kk = 0; kk < S_LEN; kk += 16) {
        float4 a0 = *(const float4*)&A[(size_t)(m0 + ar0)      * S_LEN + kk + ac];
        float4 a1 = *(const float4*)&A[(size_t)(m0 + ar0 + 64) * S_LEN + kk + ac];
        float4 b  = *(const float4*)&Bg[(size_t)(kk + br) * HDIM + bc];
        As[ac+0][ar0]    = a0.x; As[ac+1][ar0]    = a0.y; As[ac+2][ar0]    = a0.z; As[ac+3][ar0]    = a0.w;
        As[ac+0][ar0+64] = a1.x; As[ac+1][ar0+64] = a1.y; As[ac+2][ar0+64] = a1.z; As[ac+3][ar0+64] = a1.w;
        *(float4*)&Bs[br][bc] = b;
        __syncthreads();
#pragma unroll
        for (int k = 0; k < 16; k++) {
            float a[8], b2[4];
            *(float4*)&a[0]  = *(const float4*)&As[k][tm*8];
            *(float4*)&a[4]  = *(const float4*)&As[k][tm*8+4];
            *(float4*)&b2[0] = *(const float4*)&Bs[k][tn*4];
#pragma unroll
            for (int i = 0; i < 8; i++)
#pragma unroll
                for (int j = 0; j < 4; j++) acc[i][j] = fmaf(a[i], b2[j], acc[i][j]);
        }
        __syncthreads();
    }

    size_t rbase = (size_t)bh * S_LEN * HDIM;
    float lam = softplusf(lambda_reg[0]) + F_EPS;
    if (epi == 0) {
#pragma unroll
        for (int i = 0; i < 8; i++) {
            int grow = m0 + tm*8 + i;
            size_t off = rbase + (size_t)grow * HDIM + tn*4;
            float4 v4 = *(const float4*)&g_v[off];
            float4 a4 = *(const float4*)&g_alpha[off];
            float4 r = make_float4(v4.x - acc[i][0] - lam * a4.x,
                                   v4.y - acc[i][1] - lam * a4.y,
                                   v4.z - acc[i][2] - lam * a4.z,
                                   v4.w - acc[i][3] - lam * a4.w);
            *(float4*)&g_resid[off] = r;
        }
    } else {
        float xsa = xsa_scale[0];
        int b = bh >> 4, h = bh & 15;
#pragma unroll
        for (int i = 0; i < 8; i++) {
            int grow = m0 + tm*8 + i;
            size_t off = rbase + (size_t)grow * HDIM + tn*4;
            float4 v4 = *(const float4*)&g_v[off];
            float o0 = acc[i][0];
            float o1 = acc[i][1];
            float o2 = acc[i][2];
            float o3 = acc[i][3];
            float pov = o0*v4.x + o1*v4.y + o2*v4.z + o3*v4.w;
            float pvv = v4.x*v4.x + v4.y*v4.y + v4.z*v4.z + v4.w*v4.w;
#pragma unroll
            for (int sft = 8; sft; sft >>= 1) {   // reduce over the 16 lanes sharing tm
                pov += __shfl_xor_sync(0xffffffffu, pov, sft);
                pvv += __shfl_xor_sync(0xffffffffu, pvv, sft);
            }
            float c = xsa * pov / (pvv + F_EPS);
            float4 o = make_float4(o0 - c*v4.x, o1 - c*v4.y, o2 - c*v4.z, o3 - c*v4.w);
            *(float4*)&g_ctx[((size_t)b * S_LEN + grow) * DM + h * HDIM + tn*4] = o;
        }
    }
}

// ---------------- ltr partials: ltr[bh,chunk,r,d] = sum_{s in chunk} lr[h,s,r]*resid[bh,s,d] ----------------
__global__ __launch_bounds__(256) void ltr_kernel(const float* __restrict__ resid) {
    __shared__ float Rs[64][64];
    __shared__ float Ls[64][16];
    int tid = threadIdx.x;
    int bh = blockIdx.x, chunk = blockIdx.y;
    int h = bh & 15;
    int s0 = chunk * 256;
    int d = tid & 63;
    int rb = (tid >> 6) * 4;
    float acc[4] = {0.f, 0.f, 0.f, 0.f};
    size_t rbase = (size_t)bh * S_LEN * HDIM;
    for (int c = 0; c < 4; c++) {
        int sb = s0 + c * 64;
#pragma unroll
        for (int i = 0; i < 4; i++) {
            int f4 = tid + i * 256;
            int row = f4 >> 4, c4 = (f4 & 15) * 4;
            *(float4*)&Rs[row][c4] = *(const float4*)&resid[rbase + (size_t)(sb + row) * HDIM + c4];
        }
        {
            int row = tid >> 2, c4 = (tid & 3) * 4;
            *(float4*)&Ls[row][c4] = *(const float4*)&g_lr[((size_t)h * S_LEN + sb + row) * RK + c4];
        }
        __syncthreads();
#pragma unroll 8
        for (int s = 0; s < 64; s++) {
            float rv = Rs[s][d];
#pragma unroll
            for (int j = 0; j < 4; j++) acc[j] = fmaf(Ls[s][rb + j], rv, acc[j]);
        }
        __syncthreads();
    }
#pragma unroll
    for (int j = 0; j < 4; j++)
        g_ltr[(((size_t)bh * 8 + chunk) * RK + rb + j) * HDIM + d] = acc[j];
}

// ---------------- alpha update: alpha = clip(alpha + resid*dp + lr @ ltr, +-10) ----------------
__global__ __launch_bounds__(256) void update_kernel(
    const float* __restrict__ resid, int first,
    const float* __restrict__ diag_scale, const float* __restrict__ reg)
{
    __shared__ float Lt[16][64];
    __shared__ float Ls[64][16];
    int tid = threadIdx.x;
    int bh = blockIdx.x;
    int h = bh & 15;
    int s0 = blockIdx.y * 64;
#pragma unroll
    for (int i = 0; i < 4; i++) {
        int e = tid + i * 256;
        int r = e >> 6, d2 = e & 63;
        float s = 0.f;
#pragma unroll
        for (int p = 0; p < 8; p++) s += g_ltr[(((size_t)bh * 8 + p) * RK + r) * HDIM + d2];
        Lt[r][d2] = s;
    }
    {
        int row = tid >> 2, c4 = (tid & 3) * 4;
        *(float4*)&Ls[row][c4] = *(const float4*)&g_lr[((size_t)h * S_LEN + s0 + row) * RK + c4];
    }
    __syncthreads();
    float dp = 0.6931471805599453f * diag_scale[h] + reg[0];  // softplus(0)*scale + reg (diag exactly 0)
    int d = tid & 63;
    int sb = (tid >> 6) * 16;
    size_t rbase = (size_t)bh * S_LEN * HDIM;
#pragma unroll 4
    for (int ii = 0; ii < 16; ii++) {
        int sl = sb + ii;
        size_t off = rbase + (size_t)(s0 + sl) * HDIM + d;
        float r = resid[off];
        float pre = r * dp;
#pragma unroll
        for (int rr = 0; rr < 16; rr++) pre = fmaf(Ls[sl][rr], Lt[rr][d], pre);
        float aold = first ? 0.f : g_alpha[off];
        float an = aold + pre;
        g_alpha[off] = fminf(fmaxf(an, -CLIPA), CLIPA);
    }
}

// ---------------- host ----------------
extern "C" void kernel_launch(void* const* d_in, const int* in_sizes, int n_in,
                              void* d_out, int out_size)
{
    (void)in_sizes; (void)n_in; (void)out_size;
    const float* x     = (const float*)d_in[0];
    const float* w_q   = (const float*)d_in[1];
    const float* w_k   = (const float*)d_in[2];
    const float* w_v   = (const float*)d_in[3];
    const float* w_o   = (const float*)d_in[4];
    const float* bandw = (const float*)d_in[5];
    const float* dscal = (const float*)d_in[6];
    const float* pos   = (const float*)d_in[7];
    const float* hproj = (const float*)d_in[8];
    const float* reg   = (const float*)d_in[9];
    const float* lamr  = (const float*)d_in[10];
    const float* xsa   = (const float*)d_in[11];

    float *p_q, *p_k, *p_v, *p_alpha, *p_resid, *p_ctx;
    cudaGetSymbolAddress((void**)&p_q,     g_q);
    cudaGetSymbolAddress((void**)&p_k,     g_k);
    cudaGetSymbolAddress((void**)&p_v,     g_v);
    cudaGetSymbolAddress((void**)&p_alpha, g_alpha);
    cudaGetSymbolAddress((void**)&p_resid, g_resid);
    cudaGetSymbolAddress((void**)&p_ctx,   g_ctx);

    dim3 blk(256);
    dim3 gProj(DM / 128, (BSZ * S_LEN) / 128);          // (8, 32)

    gemm_nt_kernel<<<gProj, blk>>>(x, w_q, p_q, BSZ * S_LEN, DM, DM, 1);
    gemm_nt_kernel<<<gProj, blk>>>(x, w_k, p_k, BSZ * S_LEN, DM, DM, 1);
    gemm_nt_kernel<<<gProj, blk>>>(x, w_v, p_v, BSZ * S_LEN, DM, DM, 1);

    rowsq_kernel<<<16384, 256>>>();
    build_kernel<<<dim3(32, 16, 32), blk>>>(bandw);
    lr_kernel<<<(NH * S_LEN) / 256, 256>>>(pos, hproj);

    for (int it = 0; it < 8; it++) {
        const float* resid = (it == 0) ? p_v : p_resid;   // iter 0: alpha=0 -> residual = v
        if (it > 0)
            solve_gemm_kernel<<<dim3(16, 32), blk>>>(p_alpha, 0, lamr, xsa);
        ltr_kernel<<<dim3(32, 8), blk>>>(resid);
        update_kernel<<<dim3(32, 32), blk>>>(resid, it == 0 ? 1 : 0, dscal, reg);
    }

    // out = K_masked @ alpha (diag contributes exactly 0), fused XSA subtract -> g_ctx
    solve_gemm_kernel<<<dim3(16, 32), blk>>>(p_alpha, 1, lamr, xsa);

    // final projection: d_out = ctx @ w_o^T
    gemm_nt_kernel<<<gProj, blk>>>(p_ctx, w_o, (float*)d_out, BSZ * S_LEN, DM, DM, 0);
}

// round 4
// speedup vs baseline: 1.6388x; 1.6388x over previous
#include <cuda_runtime.h>
#include <cuda_bf16.h>
#include <cstdint>

#define S_LEN 2048
#define HDIM  64
#define NH    16
#define BSZ   2
#define BH    32          // BSZ*NH
#define DM    1024
#define RK    16
#define F_EPS 1e-6f
#define CLIPA 10.0f

// ---------------- scratch (device globals; no allocation allowed) ----------------
__device__ float g_q[4194304];       // [B,H,S,Dh]
__device__ float g_k[4194304];
__device__ float g_v[4194304];
__device__ __nv_bfloat16 g_kh[134217728];  // masked kernel hi [B,H,S,S] (268 MiB)
__device__ __nv_bfloat16 g_kl[134217728];  // masked kernel lo (268 MiB)
__device__ float g_qsq[65536];       // [B,H,S]
__device__ float g_ksq[65536];
__device__ float g_lr[524288];       // [H,S,RK]
__device__ float g_alpha[4194304];   // [B,H,S,Dh]
__device__ __nv_bfloat16 g_ahi[4194304];   // alpha hi bf16
__device__ __nv_bfloat16 g_alo[4194304];   // alpha lo bf16
__device__ float g_resid[4194304];   // residual; reused as partial-acc in final
__device__ float g_ltr[262144];      // [BH, 8 partials, RK, Dh]
__device__ float g_ctx[4194304];     // [B,S,H*Dh]

__device__ __forceinline__ float softplusf(float x) {
    return (x > 20.f) ? x : log1pf(__expf(x));
}

__device__ __forceinline__ uint32_t smem_u32(const void* p) {
    uint32_t a;
    asm("{ .reg .u64 t; cvta.to.shared.u64 t, %1; cvt.u32.u64 %0, t; }" : "=r"(a) : "l"(p));
    return a;
}

// ---------------- generic NT SGEMM: C[m,n] = sum_k A[m,k]*B[n,k] ----------------
__global__ __launch_bounds__(256) void gemm_nt_kernel(
    const float* __restrict__ A, const float* __restrict__ B,
    float* __restrict__ C, int M, int N, int K, int mode)
{
    __shared__ float As[16][128];
    __shared__ float Bs[16][128];
    const int tid = threadIdx.x;
    const int m0 = blockIdx.y * 128;
    const int n0 = blockIdx.x * 128;
    const int tm = tid >> 4, tn = tid & 15;
    const int lr_ = tid >> 2;
    const int lc  = (tid & 3) * 4;
    const float* Ag = A + (size_t)(m0 + lr_) * K + lc;
    const float* Bg = B + (size_t)(n0 + lr_) * K + lc;

    float acc[8][8];
#pragma unroll
    for (int i = 0; i < 8; i++)
#pragma unroll
        for (int j = 0; j < 8; j++) acc[i][j] = 0.f;

    for (int kk = 0; kk < K; kk += 16) {
        float4 a0 = *(const float4*)(Ag + kk);
        float4 a1 = *(const float4*)(Ag + (size_t)64 * K + kk);
        float4 b0 = *(const float4*)(Bg + kk);
        float4 b1 = *(const float4*)(Bg + (size_t)64 * K + kk);
        As[lc+0][lr_]    = a0.x; As[lc+1][lr_]    = a0.y; As[lc+2][lr_]    = a0.z; As[lc+3][lr_]    = a0.w;
        As[lc+0][lr_+64] = a1.x; As[lc+1][lr_+64] = a1.y; As[lc+2][lr_+64] = a1.z; As[lc+3][lr_+64] = a1.w;
        Bs[lc+0][lr_]    = b0.x; Bs[lc+1][lr_]    = b0.y; Bs[lc+2][lr_]    = b0.z; Bs[lc+3][lr_]    = b0.w;
        Bs[lc+0][lr_+64] = b1.x; Bs[lc+1][lr_+64] = b1.y; Bs[lc+2][lr_+64] = b1.z; Bs[lc+3][lr_+64] = b1.w;
        __syncthreads();
#pragma unroll
        for (int k = 0; k < 16; k++) {
            float a[8], b[8];
            *(float4*)&a[0] = *(const float4*)&As[k][tm*8];
            *(float4*)&a[4] = *(const float4*)&As[k][tm*8+4];
            *(float4*)&b[0] = *(const float4*)&Bs[k][tn*8];
            *(float4*)&b[4] = *(const float4*)&Bs[k][tn*8+4];
#pragma unroll
            for (int i = 0; i < 8; i++)
#pragma unroll
                for (int j = 0; j < 8; j++) acc[i][j] = fmaf(a[i], b[j], acc[i][j]);
        }
        __syncthreads();
    }

    if (mode == 0) {
#pragma unroll
        for (int i = 0; i < 8; i++) {
            int row = m0 + tm*8 + i;
            *(float4*)&C[(size_t)row * N + n0 + tn*8]     = make_float4(acc[i][0], acc[i][1], acc[i][2], acc[i][3]);
            *(float4*)&C[(size_t)row * N + n0 + tn*8 + 4] = make_float4(acc[i][4], acc[i][5], acc[i][6], acc[i][7]);
        }
    } else {
#pragma unroll
        for (int i = 0; i < 8; i++) {
            int row = m0 + tm*8 + i;
            int b = row >> 11, s = row & (S_LEN - 1);
            int col = n0 + tn*8;
            int h = col >> 6, d = col & 63;
            float* dst = &C[(((size_t)(b*NH + h)) * S_LEN + s) * HDIM + d];
            *(float4*)dst       = make_float4(acc[i][0], acc[i][1], acc[i][2], acc[i][3]);
            *(float4*)(dst + 4) = make_float4(acc[i][4], acc[i][5], acc[i][6], acc[i][7]);
        }
    }
}

// ---------------- per-row squared norms ----------------
__global__ void rowsq_kernel() {
    int g = blockIdx.x * blockDim.x + threadIdx.x;
    int warp = g >> 5, lane = g & 31;
    const float* src; float* dst; int row;
    if (warp < BH * S_LEN) { src = g_q; dst = g_qsq; row = warp; }
    else                   { src = g_k; dst = g_ksq; row = warp - BH * S_LEN; }
    float a = src[(size_t)row * HDIM + lane];
    float b = src[(size_t)row * HDIM + lane + 32];
    float s = a*a + b*b;
#pragma unroll
    for (int off = 16; off; off >>= 1) s += __shfl_xor_sync(0xffffffffu, s, off);
    if (lane == 0) dst[row] = s;
}

// ---------------- masked kernel build: exp RBF, diag = 0; write bf16 hi+lo ----------------
__global__ __launch_bounds__(256) void build_kernel(const float* __restrict__ bandwidth)
{
    __shared__ float Qs[64][128];
    __shared__ float Ks[64][64];
    int tid = threadIdx.x;
    int bh = blockIdx.z;
    int m0 = blockIdx.y * 128;
    int n0 = blockIdx.x * 64;
    size_t base = (size_t)bh * S_LEN * HDIM;

#pragma unroll
    for (int i = 0; i < 8; i++) {
        int f4 = tid + i * 256;
        int row = f4 >> 4, c4 = (f4 & 15) * 4;
        float4 v = *(const float4*)&g_q[base + (size_t)(m0 + row) * HDIM + c4];
        Qs[c4+0][row] = v.x; Qs[c4+1][row] = v.y; Qs[c4+2][row] = v.z; Qs[c4+3][row] = v.w;
    }
#pragma unroll
    for (int i = 0; i < 4; i++) {
        int f4 = tid + i * 256;
        int row = f4 >> 4, c4 = (f4 & 15) * 4;
        float4 v = *(const float4*)&g_k[base + (size_t)(n0 + row) * HDIM + c4];
        Ks[c4+0][row] = v.x; Ks[c4+1][row] = v.y; Ks[c4+2][row] = v.z; Ks[c4+3][row] = v.w;
    }
    __syncthreads();

    int tm = tid >> 4, tn = tid & 15;
    float acc[8][4];
#pragma unroll
    for (int i = 0; i < 8; i++)
#pragma unroll
        for (int j = 0; j < 4; j++) acc[i][j] = 0.f;

#pragma unroll 16
    for (int k = 0; k < 64; k++) {
        float a[8], b[4];
        *(float4*)&a[0] = *(const float4*)&Qs[k][tm*8];
        *(float4*)&a[4] = *(const float4*)&Qs[k][tm*8+4];
        *(float4*)&b[0] = *(const float4*)&Ks[k][tn*4];
#pragma unroll
        for (int i = 0; i < 8; i++)
#pragma unroll
            for (int j = 0; j < 4; j++) acc[i][j] = fmaf(a[i], b[j], acc[i][j]);
    }

    float bw = softplusf(bandwidth[0]) + F_EPS;
    float inv2 = 1.f / (2.f * bw * bw);
    int sbase = bh * S_LEN;
    int gcol = n0 + tn * 4;
    float4 ks4 = *(const float4*)&g_ksq[sbase + gcol];
#pragma unroll
    for (int i = 0; i < 8; i++) {
        int grow = m0 + tm*8 + i;
        float qs = g_qsq[sbase + grow];
        float o[4];
        o[0] = __expf(-fmaxf(qs + ks4.x - 2.f*acc[i][0], 0.f) * inv2);
        o[1] = __expf(-fmaxf(qs + ks4.y - 2.f*acc[i][1], 0.f) * inv2);
        o[2] = __expf(-fmaxf(qs + ks4.z - 2.f*acc[i][2], 0.f) * inv2);
        o[3] = __expf(-fmaxf(qs + ks4.w - 2.f*acc[i][3], 0.f) * inv2);
        if (grow == gcol    ) o[0] = 0.f;
        if (grow == gcol + 1) o[1] = 0.f;
        if (grow == gcol + 2) o[2] = 0.f;
        if (grow == gcol + 3) o[3] = 0.f;
        __nv_bfloat16 hi[4], lo[4];
#pragma unroll
        for (int j = 0; j < 4; j++) {
            hi[j] = __float2bfloat16_rn(o[j]);
            lo[j] = __float2bfloat16_rn(o[j] - __bfloat162float(hi[j]));
        }
        size_t eoff = ((size_t)bh * S_LEN + grow) * S_LEN + gcol;
        *(uint2*)&g_kh[eoff] = *(uint2*)hi;
        *(uint2*)&g_kl[eoff] = *(uint2*)lo;
    }
}

// ---------------- lr[h,s,t] = sum_r pos[s,r] * proj[h,r,t] ----------------
__global__ void lr_kernel(const float* __restrict__ pos, const float* __restrict__ proj) {
    int idx = blockIdx.x * blockDim.x + threadIdx.x;
    int h = idx >> 11, s = idx & (S_LEN - 1);
    float p[16];
#pragma unroll
    for (int i = 0; i < 4; i++) *(float4*)&p[i*4] = *(const float4*)&pos[(size_t)s * RK + i*4];
    const float* pr = proj + (size_t)h * RK * RK;
    float out[16];
#pragma unroll
    for (int t = 0; t < 16; t++) {
        float sum = 0.f;
#pragma unroll
        for (int r = 0; r < 16; r++) sum = fmaf(p[r], pr[r*16 + t], sum);
        out[t] = sum;
    }
#pragma unroll
    for (int i = 0; i < 4; i++)
        *(float4*)&g_lr[((size_t)h * S_LEN + s) * RK + i*4] = *(float4*)&out[i*4];
}

// ======================================================================
// Tensor-core solve: acc = A(bf16)[bh] @ (alpha_hi + alpha_lo)  (M2048 N64 K2048)
// epi 0: g_resid = v - acc - lam*alpha
// epi 2: g_resid = acc                    (partial, A = K_hi)
// epi 3: out = acc + g_resid ; XSA subtract ; write g_ctx    (A = K_lo)
// ======================================================================
#define SOLVE_SMEM ((2*128*72 + 2*64*72 + 2*64*72) * 2)

__global__ __launch_bounds__(256) void solve_mma_kernel(
    const __nv_bfloat16* __restrict__ A, int epi,
    const float* __restrict__ lambda_reg, const float* __restrict__ xsa_scale)
{
    extern __shared__ __nv_bfloat16 sm[];
    // layout: As [2][128][72] | Bh [2][64][72] | Bl [2][64][72]
    const uint32_t sbase = smem_u32(sm);
    const uint32_t bh_off = 2*128*72*2;          // byte offsets
    const uint32_t bl_off = bh_off + 2*64*72*2;

    const int tid = threadIdx.x;
    const int bh = blockIdx.y;
    const int m0 = blockIdx.x * 128;
    const int lane = tid & 31, wid = tid >> 5;

    // cp.async source setup
    const int ar = tid >> 1, ac = (tid & 1) * 32;         // A: row, col-chunk (32 elems = 64 B)
    const int bkr = tid >> 2, bc = (tid & 3) * 16;        // B: k-row, col-chunk (16 elems = 32 B)
    const __nv_bfloat16* ag  = A     + ((size_t)bh*S_LEN + m0 + ar) * S_LEN + ac;
    const __nv_bfloat16* bhg = g_ahi + ((size_t)bh*S_LEN + bkr) * HDIM + bc;
    const __nv_bfloat16* blg = g_alo + ((size_t)bh*S_LEN + bkr) * HDIM + bc;
    const uint32_t da_base = sbase + (uint32_t)((ar*72 + ac) * 2);
    const uint32_t db_base = sbase + bh_off + (uint32_t)((bkr*72 + bc) * 2);
    const uint32_t dl_base = sbase + bl_off + (uint32_t)((bkr*72 + bc) * 2);

// A: 64 bytes per thread -> FOUR contiguous 16B cp.async (R3 bug: only 2, holes -> NaN)
#define LOAD_STAGE(k0, st) do {                                                        \
        uint32_t _da = da_base + (st) * (128*72*2);                                    \
        const __nv_bfloat16* _ap = ag + (k0);                                          \
        asm volatile("cp.async.ca.shared.global [%0],[%1],16;\n"                       \
                     "cp.async.ca.shared.global [%2],[%3],16;\n"                       \
                     "cp.async.ca.shared.global [%4],[%5],16;\n"                       \
                     "cp.async.ca.shared.global [%6],[%7],16;\n"                       \
                     :: "r"(_da),    "l"(_ap),                                         \
                        "r"(_da+16), "l"(_ap+8),                                       \
                        "r"(_da+32), "l"(_ap+16),                                      \
                        "r"(_da+48), "l"(_ap+24) : "memory");                          \
        uint32_t _db = db_base + (st) * (64*72*2);                                     \
        const __nv_bfloat16* _bp = bhg + (size_t)(k0) * HDIM;                          \
        asm volatile("cp.async.ca.shared.global [%0],[%1],16;\n"                       \
                     "cp.async.ca.shared.global [%2],[%3],16;\n"                       \
                     :: "r"(_db), "l"(_bp), "r"(_db+16), "l"(_bp+8) : "memory");       \
        uint32_t _dl = dl_base + (st) * (64*72*2);                                     \
        const __nv_bfloat16* _lp = blg + (size_t)(k0) * HDIM;                          \
        asm volatile("cp.async.ca.shared.global [%0],[%1],16;\n"                       \
                     "cp.async.ca.shared.global [%2],[%3],16;\n"                       \
                     :: "r"(_dl), "l"(_lp), "r"(_dl+16), "l"(_lp+8) : "memory");       \
        asm volatile("cp.async.commit_group;" ::: "memory");                           \
    } while (0)

    float acc[8][4];
#pragma unroll
    for (int i = 0; i < 8; i++)
#pragma unroll
        for (int j = 0; j < 4; j++) acc[i][j] = 0.f;

    const int g = lane & 7, mt = lane >> 3;
    const int a_row = wid*16 + g + (mt & 1)*8;
    const int a_coladd = (mt >> 1)*8;
    const int b_rowadd = (mt & 1)*8 + g;
    const int b_coladd = (mt >> 1)*8;

    LOAD_STAGE(0, 0);

    for (int it = 0; it < 32; it++) {
        if (it + 1 < 32) LOAD_STAGE((it+1)*64, (it+1) & 1);
        if (it + 1 < 32) asm volatile("cp.async.wait_group 1;" ::: "memory");
        else             asm volatile("cp.async.wait_group 0;" ::: "memory");
        __syncthreads();

        const int st = it & 1;
        const uint32_t a_stage = sbase + st * (128*72*2);
        const uint32_t bh_stage = sbase + bh_off + st * (64*72*2);
        const uint32_t bl_stage = sbase + bl_off + st * (64*72*2);

#pragma unroll
        for (int kc = 0; kc < 4; kc++) {
            uint32_t a0, a1, a2, a3;
            {
                uint32_t aaddr = a_stage + (uint32_t)((a_row*72 + kc*16 + a_coladd) * 2);
                asm volatile("ldmatrix.sync.aligned.m8n8.x4.shared.b16 {%0,%1,%2,%3}, [%4];"
                             : "=r"(a0), "=r"(a1), "=r"(a2), "=r"(a3) : "r"(aaddr));
            }
            uint32_t bhr[8][2], blr[8][2];
#pragma unroll
            for (int p = 0; p < 4; p++) {
                uint32_t brow = (uint32_t)(((kc*16 + b_rowadd)*72 + p*16 + b_coladd) * 2);
                uint32_t baddr = bh_stage + brow;
                asm volatile("ldmatrix.sync.aligned.m8n8.x4.trans.shared.b16 {%0,%1,%2,%3}, [%4];"
                             : "=r"(bhr[2*p][0]), "=r"(bhr[2*p][1]),
                               "=r"(bhr[2*p+1][0]), "=r"(bhr[2*p+1][1]) : "r"(baddr));
                uint32_t laddr = bl_stage + brow;
                asm volatile("ldmatrix.sync.aligned.m8n8.x4.trans.shared.b16 {%0,%1,%2,%3}, [%4];"
                             : "=r"(blr[2*p][0]), "=r"(blr[2*p][1]),
                               "=r"(blr[2*p+1][0]), "=r"(blr[2*p+1][1]) : "r"(laddr));
            }
#pragma unroll
            for (int nf = 0; nf < 8; nf++) {
                asm volatile("mma.sync.aligned.m16n8k16.row.col.f32.bf16.bf16.f32 "
                             "{%0,%1,%2,%3}, {%4,%5,%6,%7}, {%8,%9}, {%0,%1,%2,%3};"
                             : "+f"(acc[nf][0]), "+f"(acc[nf][1]), "+f"(acc[nf][2]), "+f"(acc[nf][3])
                             : "r"(a0), "r"(a1), "r"(a2), "r"(a3), "r"(bhr[nf][0]), "r"(bhr[nf][1]));
                asm volatile("mma.sync.aligned.m16n8k16.row.col.f32.bf16.bf16.f32 "
                             "{%0,%1,%2,%3}, {%4,%5,%6,%7}, {%8,%9}, {%0,%1,%2,%3};"
                             : "+f"(acc[nf][0]), "+f"(acc[nf][1]), "+f"(acc[nf][2]), "+f"(acc[nf][3])
                             : "r"(a0), "r"(a1), "r"(a2), "r"(a3), "r"(blr[nf][0]), "r"(blr[nf][1]));
            }
        }
        __syncthreads();
    }

    // ---------------- epilogue ----------------
    size_t rbase = (size_t)bh * S_LEN * HDIM;
    int row0 = m0 + wid*16 + (lane >> 2);
    int colb = (lane & 3) * 2;

    if (epi == 0) {
        float lam = softplusf(lambda_reg[0]) + F_EPS;
#pragma unroll
        for (int hh = 0; hh < 2; hh++) {
            int row = row0 + hh*8;
#pragma unroll
            for (int nf = 0; nf < 8; nf++) {
                size_t off = rbase + (size_t)row * HDIM + nf*8 + colb;
                float2 v2 = *(const float2*)&g_v[off];
                float2 a2 = *(const float2*)&g_alpha[off];
                float2 r;
                r.x = v2.x - acc[nf][hh*2+0] - lam * a2.x;
                r.y = v2.y - acc[nf][hh*2+1] - lam * a2.y;
                *(float2*)&g_resid[off] = r;
            }
        }
    } else if (epi == 2) {
#pragma unroll
        for (int hh = 0; hh < 2; hh++) {
            int row = row0 + hh*8;
#pragma unroll
            for (int nf = 0; nf < 8; nf++) {
                size_t off = rbase + (size_t)row * HDIM + nf*8 + colb;
                *(float2*)&g_resid[off] = make_float2(acc[nf][hh*2+0], acc[nf][hh*2+1]);
            }
        }
    } else {  // epi == 3: acc += partial; XSA subtract; write ctx
        float xsa = xsa_scale[0];
        int b = bh >> 4, h = bh & 15;
#pragma unroll
        for (int hh = 0; hh < 2; hh++) {
            int row = row0 + hh*8;
            float o[8][2], vv[8][2];
            float pov = 0.f, pvv = 0.f;
#pragma unroll
            for (int nf = 0; nf < 8; nf++) {
                size_t off = rbase + (size_t)row * HDIM + nf*8 + colb;
                float2 p2 = *(const float2*)&g_resid[off];
                float2 v2 = *(const float2*)&g_v[off];
                o[nf][0] = acc[nf][hh*2+0] + p2.x;
                o[nf][1] = acc[nf][hh*2+1] + p2.y;
                vv[nf][0] = v2.x; vv[nf][1] = v2.y;
                pov += o[nf][0]*v2.x + o[nf][1]*v2.y;
                pvv += v2.x*v2.x + v2.y*v2.y;
            }
            pov += __shfl_xor_sync(0xffffffffu, pov, 1);
            pvv += __shfl_xor_sync(0xffffffffu, pvv, 1);
            pov += __shfl_xor_sync(0xffffffffu, pov, 2);
            pvv += __shfl_xor_sync(0xffffffffu, pvv, 2);
            float c = xsa * pov / (pvv + F_EPS);
#pragma unroll
            for (int nf = 0; nf < 8; nf++) {
                float2 w;
                w.x = o[nf][0] - c * vv[nf][0];
                w.y = o[nf][1] - c * vv[nf][1];
                *(float2*)&g_ctx[((size_t)b * S_LEN + row) * DM + h * HDIM + nf*8 + colb] = w;
            }
        }
    }
#undef LOAD_STAGE
}

// ---------------- ltr partials ----------------
__global__ __launch_bounds__(256) void ltr_kernel(const float* __restrict__ resid) {
    __shared__ float Rs[64][64];
    __shared__ float Ls[64][16];
    int tid = threadIdx.x;
    int bh = blockIdx.x, chunk = blockIdx.y;
    int h = bh & 15;
    int s0 = chunk * 256;
    int d = tid & 63;
    int rb = (tid >> 6) * 4;
    float acc[4] = {0.f, 0.f, 0.f, 0.f};
    size_t rbase = (size_t)bh * S_LEN * HDIM;
    for (int c = 0; c < 4; c++) {
        int sb = s0 + c * 64;
#pragma unroll
        for (int i = 0; i < 4; i++) {
            int f4 = tid + i * 256;
            int row = f4 >> 4, c4 = (f4 & 15) * 4;
            *(float4*)&Rs[row][c4] = *(const float4*)&resid[rbase + (size_t)(sb + row) * HDIM + c4];
        }
        {
            int row = tid >> 2, c4 = (tid & 3) * 4;
            *(float4*)&Ls[row][c4] = *(const float4*)&g_lr[((size_t)h * S_LEN + sb + row) * RK + c4];
        }
        __syncthreads();
#pragma unroll 8
        for (int s = 0; s < 64; s++) {
            float rv = Rs[s][d];
#pragma unroll
            for (int j = 0; j < 4; j++) acc[j] = fmaf(Ls[s][rb + j], rv, acc[j]);
        }
        __syncthreads();
    }
#pragma unroll
    for (int j = 0; j < 4; j++)
        g_ltr[(((size_t)bh * 8 + chunk) * RK + rb + j) * HDIM + d] = acc[j];
}

// ---------------- alpha update; also emit bf16 hi/lo of alpha ----------------
__global__ __launch_bounds__(256) void update_kernel(
    const float* __restrict__ resid, int first,
    const float* __restrict__ diag_scale, const float* __restrict__ reg)
{
    __shared__ float Lt[16][64];
    __shared__ float Ls[64][16];
    int tid = threadIdx.x;
    int bh = blockIdx.x;
    int h = bh & 15;
    int s0 = blockIdx.y * 64;
#pragma unroll
    for (int i = 0; i < 4; i++) {
        int e = tid + i * 256;
        int r = e >> 6, d2 = e & 63;
        float s = 0.f;
#pragma unroll
        for (int p = 0; p < 8; p++) s += g_ltr[(((size_t)bh * 8 + p) * RK + r) * HDIM + d2];
        Lt[r][d2] = s;
    }
    {
        int row = tid >> 2, c4 = (tid & 3) * 4;
        *(float4*)&Ls[row][c4] = *(const float4*)&g_lr[((size_t)h * S_LEN + s0 + row) * RK + c4];
    }
    __syncthreads();
    float dp = 0.6931471805599453f * diag_scale[h] + reg[0];
    int d = tid & 63;
    int sb = (tid >> 6) * 16;
    size_t rbase = (size_t)bh * S_LEN * HDIM;
#pragma unroll 4
    for (int ii = 0; ii < 16; ii++) {
        int sl = sb + ii;
        size_t off = rbase + (size_t)(s0 + sl) * HDIM + d;
        float r = resid[off];
        float pre = r * dp;
#pragma unroll
        for (int rr = 0; rr < 16; rr++) pre = fmaf(Ls[sl][rr], Lt[rr][d], pre);
        float aold = first ? 0.f : g_alpha[off];
        float an = fminf(fmaxf(aold + pre, -CLIPA), CLIPA);
        g_alpha[off] = an;
        __nv_bfloat16 hi = __float2bfloat16_rn(an);
        g_ahi[off] = hi;
        g_alo[off] = __float2bfloat16_rn(an - __bfloat162float(hi));
    }
}

// ---------------- host ----------------
extern "C" void kernel_launch(void* const* d_in, const int* in_sizes, int n_in,
                              void* d_out, int out_size)
{
    (void)in_sizes; (void)n_in; (void)out_size;
    const float* x     = (const float*)d_in[0];
    const float* w_q   = (const float*)d_in[1];
    const float* w_k   = (const float*)d_in[2];
    const float* w_v   = (const float*)d_in[3];
    const float* w_o   = (const float*)d_in[4];
    const float* bandw = (const float*)d_in[5];
    const float* dscal = (const float*)d_in[6];
    const float* pos   = (const float*)d_in[7];
    const float* hproj = (const float*)d_in[8];
    const float* reg   = (const float*)d_in[9];
    const float* lamr  = (const float*)d_in[10];
    const float* xsa   = (const float*)d_in[11];

    float *p_q, *p_k, *p_v, *p_alpha, *p_resid, *p_ctx;
    __nv_bfloat16 *p_kh, *p_kl;
    cudaGetSymbolAddress((void**)&p_q,     g_q);
    cudaGetSymbolAddress((void**)&p_k,     g_k);
    cudaGetSymbolAddress((void**)&p_v,     g_v);
    cudaGetSymbolAddress((void**)&p_alpha, g_alpha);
    cudaGetSymbolAddress((void**)&p_resid, g_resid);
    cudaGetSymbolAddress((void**)&p_ctx,   g_ctx);
    cudaGetSymbolAddress((void**)&p_kh,    g_kh);
    cudaGetSymbolAddress((void**)&p_kl,    g_kl);

    static int smem_set = 0;
    if (!smem_set) {
        cudaFuncSetAttribute(solve_mma_kernel,
                             cudaFuncAttributeMaxDynamicSharedMemorySize, SOLVE_SMEM);
        smem_set = 1;
    }

    dim3 blk(256);
    dim3 gProj(DM / 128, (BSZ * S_LEN) / 128);

    gemm_nt_kernel<<<gProj, blk>>>(x, w_q, p_q, BSZ * S_LEN, DM, DM, 1);
    gemm_nt_kernel<<<gProj, blk>>>(x, w_k, p_k, BSZ * S_LEN, DM, DM, 1);
    gemm_nt_kernel<<<gProj, blk>>>(x, w_v, p_v, BSZ * S_LEN, DM, DM, 1);

    rowsq_kernel<<<16384, 256>>>();
    build_kernel<<<dim3(32, 16, 32), blk>>>(bandw);
    lr_kernel<<<(NH * S_LEN) / 256, 256>>>(pos, hproj);

    for (int it = 0; it < 8; it++) {
        const float* resid = (it == 0) ? p_v : p_resid;
        if (it > 0)
            solve_mma_kernel<<<dim3(16, 32), blk, SOLVE_SMEM>>>(p_kh, 0, lamr, xsa);
        ltr_kernel<<<dim3(32, 8), blk>>>(resid);
        update_kernel<<<dim3(32, 32), blk>>>(resid, it == 0 ? 1 : 0, dscal, reg);
    }

    // Final: out = (K_hi + K_lo) @ (alpha_hi + alpha_lo), fused XSA -> g_ctx
    solve_mma_kernel<<<dim3(16, 32), blk, SOLVE_SMEM>>>(p_kh, 2, lamr, xsa);
    solve_mma_kernel<<<dim3(16, 32), blk, SOLVE_SMEM>>>(p_kl, 3, lamr, xsa);

    gemm_nt_kernel<<<gProj, blk>>>(p_ctx, w_o, (float*)d_out, BSZ * S_LEN, DM, DM, 0);
}

// round 5
// speedup vs baseline: 2.0992x; 1.2810x over previous
#include <cuda_runtime.h>
#include <cuda_bf16.h>
#include <cstdint>

#define S_LEN 2048
#define HDIM  64
#define NH    16
#define BSZ   2
#define BH    32          // BSZ*NH
#define DM    1024
#define RK    16
#define F_EPS 1e-6f
#define CLIPA 10.0f

// ---------------- scratch (device globals; no allocation allowed) ----------------
__device__ float g_q[4194304];       // [B,H,S,Dh]
__device__ float g_k[4194304];
__device__ float g_v[4194304];
__device__ __nv_bfloat16 g_kh[134217728];  // masked kernel hi [B,H,S,S] (268 MiB)
__device__ __nv_bfloat16 g_kl[134217728];  // masked kernel lo (268 MiB)
__device__ float g_qsq[65536];       // [B,H,S]
__device__ float g_ksq[65536];
__device__ float g_lr[524288];       // [H,S,RK]
__device__ float g_alpha[4194304];   // [B,H,S,Dh]
__device__ __nv_bfloat16 g_ahi[4194304];   // alpha hi bf16
__device__ __nv_bfloat16 g_alo[4194304];   // alpha lo bf16
__device__ float g_resid[4194304];   // residual; reused as partial-acc in final
__device__ float g_ltr[262144];      // [BH, 8 partials, RK, Dh]
__device__ float g_ctx[4194304];     // [B,S,H*Dh]

__device__ __forceinline__ float softplusf(float x) {
    return (x > 20.f) ? x : log1pf(__expf(x));
}

__device__ __forceinline__ uint32_t smem_u32(const void* p) {
    uint32_t a;
    asm("{ .reg .u64 t; cvta.to.shared.u64 t, %1; cvt.u32.u64 %0, t; }" : "=r"(a) : "l"(p));
    return a;
}

// ---------------- generic NT SGEMM: C[m,n] = sum_k A[m,k]*B[n,k] ----------------
__global__ __launch_bounds__(256) void gemm_nt_kernel(
    const float* __restrict__ A, const float* __restrict__ B,
    float* __restrict__ C, int M, int N, int K, int mode)
{
    __shared__ float As[16][128];
    __shared__ float Bs[16][128];
    const int tid = threadIdx.x;
    const int m0 = blockIdx.y * 128;
    const int n0 = blockIdx.x * 128;
    const int tm = tid >> 4, tn = tid & 15;
    const int lr_ = tid >> 2;
    const int lc  = (tid & 3) * 4;
    const float* Ag = A + (size_t)(m0 + lr_) * K + lc;
    const float* Bg = B + (size_t)(n0 + lr_) * K + lc;

    float acc[8][8];
#pragma unroll
    for (int i = 0; i < 8; i++)
#pragma unroll
        for (int j = 0; j < 8; j++) acc[i][j] = 0.f;

    for (int kk = 0; kk < K; kk += 16) {
        float4 a0 = *(const float4*)(Ag + kk);
        float4 a1 = *(const float4*)(Ag + (size_t)64 * K + kk);
        float4 b0 = *(const float4*)(Bg + kk);
        float4 b1 = *(const float4*)(Bg + (size_t)64 * K + kk);
        As[lc+0][lr_]    = a0.x; As[lc+1][lr_]    = a0.y; As[lc+2][lr_]    = a0.z; As[lc+3][lr_]    = a0.w;
        As[lc+0][lr_+64] = a1.x; As[lc+1][lr_+64] = a1.y; As[lc+2][lr_+64] = a1.z; As[lc+3][lr_+64] = a1.w;
        Bs[lc+0][lr_]    = b0.x; Bs[lc+1][lr_]    = b0.y; Bs[lc+2][lr_]    = b0.z; Bs[lc+3][lr_]    = b0.w;
        Bs[lc+0][lr_+64] = b1.x; Bs[lc+1][lr_+64] = b1.y; Bs[lc+2][lr_+64] = b1.z; Bs[lc+3][lr_+64] = b1.w;
        __syncthreads();
#pragma unroll
        for (int k = 0; k < 16; k++) {
            float a[8], b[8];
            *(float4*)&a[0] = *(const float4*)&As[k][tm*8];
            *(float4*)&a[4] = *(const float4*)&As[k][tm*8+4];
            *(float4*)&b[0] = *(const float4*)&Bs[k][tn*8];
            *(float4*)&b[4] = *(const float4*)&Bs[k][tn*8+4];
#pragma unroll
            for (int i = 0; i < 8; i++)
#pragma unroll
                for (int j = 0; j < 8; j++) acc[i][j] = fmaf(a[i], b[j], acc[i][j]);
        }
        __syncthreads();
    }

    if (mode == 0) {
#pragma unroll
        for (int i = 0; i < 8; i++) {
            int row = m0 + tm*8 + i;
            *(float4*)&C[(size_t)row * N + n0 + tn*8]     = make_float4(acc[i][0], acc[i][1], acc[i][2], acc[i][3]);
            *(float4*)&C[(size_t)row * N + n0 + tn*8 + 4] = make_float4(acc[i][4], acc[i][5], acc[i][6], acc[i][7]);
        }
    } else {
#pragma unroll
        for (int i = 0; i < 8; i++) {
            int row = m0 + tm*8 + i;
            int b = row >> 11, s = row & (S_LEN - 1);
            int col = n0 + tn*8;
            int h = col >> 6, d = col & 63;
            float* dst = &C[(((size_t)(b*NH + h)) * S_LEN + s) * HDIM + d];
            *(float4*)dst       = make_float4(acc[i][0], acc[i][1], acc[i][2], acc[i][3]);
            *(float4*)(dst + 4) = make_float4(acc[i][4], acc[i][5], acc[i][6], acc[i][7]);
        }
    }
}

// ---------------- per-row squared norms ----------------
__global__ void rowsq_kernel() {
    int g = blockIdx.x * blockDim.x + threadIdx.x;
    int warp = g >> 5, lane = g & 31;
    const float* src; float* dst; int row;
    if (warp < BH * S_LEN) { src = g_q; dst = g_qsq; row = warp; }
    else                   { src = g_k; dst = g_ksq; row = warp - BH * S_LEN; }
    float a = src[(size_t)row * HDIM + lane];
    float b = src[(size_t)row * HDIM + lane + 32];
    float s = a*a + b*b;
#pragma unroll
    for (int off = 16; off; off >>= 1) s += __shfl_xor_sync(0xffffffffu, s, off);
    if (lane == 0) dst[row] = s;
}

// ---------------- masked kernel build: exp RBF, diag = 0; write bf16 hi+lo ----------------
__global__ __launch_bounds__(256) void build_kernel(const float* __restrict__ bandwidth)
{
    __shared__ float Qs[64][128];
    __shared__ float Ks[64][64];
    int tid = threadIdx.x;
    int bh = blockIdx.z;
    int m0 = blockIdx.y * 128;
    int n0 = blockIdx.x * 64;
    size_t base = (size_t)bh * S_LEN * HDIM;

#pragma unroll
    for (int i = 0; i < 8; i++) {
        int f4 = tid + i * 256;
        int row = f4 >> 4, c4 = (f4 & 15) * 4;
        float4 v = *(const float4*)&g_q[base + (size_t)(m0 + row) * HDIM + c4];
        Qs[c4+0][row] = v.x; Qs[c4+1][row] = v.y; Qs[c4+2][row] = v.z; Qs[c4+3][row] = v.w;
    }
#pragma unroll
    for (int i = 0; i < 4; i++) {
        int f4 = tid + i * 256;
        int row = f4 >> 4, c4 = (f4 & 15) * 4;
        float4 v = *(const float4*)&g_k[base + (size_t)(n0 + row) * HDIM + c4];
        Ks[c4+0][row] = v.x; Ks[c4+1][row] = v.y; Ks[c4+2][row] = v.z; Ks[c4+3][row] = v.w;
    }
    __syncthreads();

    int tm = tid >> 4, tn = tid & 15;
    float acc[8][4];
#pragma unroll
    for (int i = 0; i < 8; i++)
#pragma unroll
        for (int j = 0; j < 4; j++) acc[i][j] = 0.f;

#pragma unroll 16
    for (int k = 0; k < 64; k++) {
        float a[8], b[4];
        *(float4*)&a[0] = *(const float4*)&Qs[k][tm*8];
        *(float4*)&a[4] = *(const float4*)&Qs[k][tm*8+4];
        *(float4*)&b[0] = *(const float4*)&Ks[k][tn*4];
#pragma unroll
        for (int i = 0; i < 8; i++)
#pragma unroll
            for (int j = 0; j < 4; j++) acc[i][j] = fmaf(a[i], b[j], acc[i][j]);
    }

    float bw = softplusf(bandwidth[0]) + F_EPS;
    float inv2 = 1.f / (2.f * bw * bw);
    int sbase = bh * S_LEN;
    int gcol = n0 + tn * 4;
    float4 ks4 = *(const float4*)&g_ksq[sbase + gcol];
#pragma unroll
    for (int i = 0; i < 8; i++) {
        int grow = m0 + tm*8 + i;
        float qs = g_qsq[sbase + grow];
        float o[4];
        o[0] = __expf(-fmaxf(qs + ks4.x - 2.f*acc[i][0], 0.f) * inv2);
        o[1] = __expf(-fmaxf(qs + ks4.y - 2.f*acc[i][1], 0.f) * inv2);
        o[2] = __expf(-fmaxf(qs + ks4.z - 2.f*acc[i][2], 0.f) * inv2);
        o[3] = __expf(-fmaxf(qs + ks4.w - 2.f*acc[i][3], 0.f) * inv2);
        if (grow == gcol    ) o[0] = 0.f;
        if (grow == gcol + 1) o[1] = 0.f;
        if (grow == gcol + 2) o[2] = 0.f;
        if (grow == gcol + 3) o[3] = 0.f;
        __nv_bfloat16 hi[4], lo[4];
#pragma unroll
        for (int j = 0; j < 4; j++) {
            hi[j] = __float2bfloat16_rn(o[j]);
            lo[j] = __float2bfloat16_rn(o[j] - __bfloat162float(hi[j]));
        }
        size_t eoff = ((size_t)bh * S_LEN + grow) * S_LEN + gcol;
        *(uint2*)&g_kh[eoff] = *(uint2*)hi;
        *(uint2*)&g_kl[eoff] = *(uint2*)lo;
    }
}

// ---------------- lr[h,s,t] = sum_r pos[s,r] * proj[h,r,t] ----------------
__global__ void lr_kernel(const float* __restrict__ pos, const float* __restrict__ proj) {
    int idx = blockIdx.x * blockDim.x + threadIdx.x;
    int h = idx >> 11, s = idx & (S_LEN - 1);
    float p[16];
#pragma unroll
    for (int i = 0; i < 4; i++) *(float4*)&p[i*4] = *(const float4*)&pos[(size_t)s * RK + i*4];
    const float* pr = proj + (size_t)h * RK * RK;
    float out[16];
#pragma unroll
    for (int t = 0; t < 16; t++) {
        float sum = 0.f;
#pragma unroll
        for (int r = 0; r < 16; r++) sum = fmaf(p[r], pr[r*16 + t], sum);
        out[t] = sum;
    }
#pragma unroll
    for (int i = 0; i < 4; i++)
        *(float4*)&g_lr[((size_t)h * S_LEN + s) * RK + i*4] = *(float4*)&out[i*4];
}

// ======================================================================
// Tensor-core solve: acc = A(bf16)[bh] @ alpha_hi [+ alpha_lo if USE_LO]
// (M2048 N64 K2048)
// epi 0: g_resid = v - acc - lam*alpha
// epi 2: g_resid = acc                    (partial, A = K_hi, USE_LO=1)
// epi 3: out = acc + g_resid ; XSA subtract ; write g_ctx    (A = K_lo, hi only)
// ======================================================================
#define SOLVE_SMEM_LO ((2*128*72 + 2*64*72 + 2*64*72) * 2)
#define SOLVE_SMEM_HI ((2*128*72 + 2*64*72) * 2)

template<bool USE_LO>
__global__ __launch_bounds__(256) void solve_mma_kernel(
    const __nv_bfloat16* __restrict__ A, int epi,
    const float* __restrict__ lambda_reg, const float* __restrict__ xsa_scale)
{
    extern __shared__ __nv_bfloat16 sm[];
    // layout: As [2][128][72] | Bh [2][64][72] | (Bl [2][64][72] if USE_LO)
    const uint32_t sbase = smem_u32(sm);
    const uint32_t bh_off = 2*128*72*2;          // byte offsets
    const uint32_t bl_off = bh_off + 2*64*72*2;

    const int tid = threadIdx.x;
    const int bh = blockIdx.y;
    const int m0 = blockIdx.x * 128;
    const int lane = tid & 31, wid = tid >> 5;

    const int ar = tid >> 1, ac = (tid & 1) * 32;         // A: row, 32-elem chunk
    const int bkr = tid >> 2, bc = (tid & 3) * 16;        // B: k-row, 16-elem chunk
    const __nv_bfloat16* ag  = A     + ((size_t)bh*S_LEN + m0 + ar) * S_LEN + ac;
    const __nv_bfloat16* bhg = g_ahi + ((size_t)bh*S_LEN + bkr) * HDIM + bc;
    const __nv_bfloat16* blg = g_alo + ((size_t)bh*S_LEN + bkr) * HDIM + bc;
    const uint32_t da_base = sbase + (uint32_t)((ar*72 + ac) * 2);
    const uint32_t db_base = sbase + bh_off + (uint32_t)((bkr*72 + bc) * 2);
    const uint32_t dl_base = sbase + bl_off + (uint32_t)((bkr*72 + bc) * 2);

#define LOAD_STAGE(k0, st) do {                                                        \
        uint32_t _da = da_base + (st) * (128*72*2);                                    \
        const __nv_bfloat16* _ap = ag + (k0);                                          \
        asm volatile("cp.async.cg.shared.global [%0],[%1],16;\n"                       \
                     "cp.async.cg.shared.global [%2],[%3],16;\n"                       \
                     "cp.async.cg.shared.global [%4],[%5],16;\n"                       \
                     "cp.async.cg.shared.global [%6],[%7],16;\n"                       \
                     :: "r"(_da),    "l"(_ap),                                         \
                        "r"(_da+16), "l"(_ap+8),                                       \
                        "r"(_da+32), "l"(_ap+16),                                      \
                        "r"(_da+48), "l"(_ap+24) : "memory");                          \
        uint32_t _db = db_base + (st) * (64*72*2);                                     \
        const __nv_bfloat16* _bp = bhg + (size_t)(k0) * HDIM;                          \
        asm volatile("cp.async.ca.shared.global [%0],[%1],16;\n"                       \
                     "cp.async.ca.shared.global [%2],[%3],16;\n"                       \
                     :: "r"(_db), "l"(_bp), "r"(_db+16), "l"(_bp+8) : "memory");       \
        if (USE_LO) {                                                                  \
            uint32_t _dl = dl_base + (st) * (64*72*2);                                 \
            const __nv_bfloat16* _lp = blg + (size_t)(k0) * HDIM;                      \
            asm volatile("cp.async.ca.shared.global [%0],[%1],16;\n"                   \
                         "cp.async.ca.shared.global [%2],[%3],16;\n"                   \
                         :: "r"(_dl), "l"(_lp), "r"(_dl+16), "l"(_lp+8) : "memory");   \
        }                                                                              \
        asm volatile("cp.async.commit_group;" ::: "memory");                           \
    } while (0)

    float acc[8][4];
#pragma unroll
    for (int i = 0; i < 8; i++)
#pragma unroll
        for (int j = 0; j < 4; j++) acc[i][j] = 0.f;

    const int g = lane & 7, mt = lane >> 3;
    const int a_row = wid*16 + g + (mt & 1)*8;
    const int a_coladd = (mt >> 1)*8;
    const int b_rowadd = (mt & 1)*8 + g;
    const int b_coladd = (mt >> 1)*8;

    LOAD_STAGE(0, 0);

    for (int it = 0; it < 32; it++) {
        if (it + 1 < 32) LOAD_STAGE((it+1)*64, (it+1) & 1);
        if (it + 1 < 32) asm volatile("cp.async.wait_group 1;" ::: "memory");
        else             asm volatile("cp.async.wait_group 0;" ::: "memory");
        __syncthreads();

        const int st = it & 1;
        const uint32_t a_stage = sbase + st * (128*72*2);
        const uint32_t bh_stage = sbase + bh_off + st * (64*72*2);
        const uint32_t bl_stage = sbase + bl_off + st * (64*72*2);

#pragma unroll
        for (int kc = 0; kc < 4; kc++) {
            uint32_t a0, a1, a2, a3;
            {
                uint32_t aaddr = a_stage + (uint32_t)((a_row*72 + kc*16 + a_coladd) * 2);
                asm volatile("ldmatrix.sync.aligned.m8n8.x4.shared.b16 {%0,%1,%2,%3}, [%4];"
                             : "=r"(a0), "=r"(a1), "=r"(a2), "=r"(a3) : "r"(aaddr));
            }
            uint32_t bhr[8][2];
#pragma unroll
            for (int p = 0; p < 4; p++) {
                uint32_t brow = (uint32_t)(((kc*16 + b_rowadd)*72 + p*16 + b_coladd) * 2);
                uint32_t baddr = bh_stage + brow;
                asm volatile("ldmatrix.sync.aligned.m8n8.x4.trans.shared.b16 {%0,%1,%2,%3}, [%4];"
                             : "=r"(bhr[2*p][0]), "=r"(bhr[2*p][1]),
                               "=r"(bhr[2*p+1][0]), "=r"(bhr[2*p+1][1]) : "r"(baddr));
            }
#pragma unroll
            for (int nf = 0; nf < 8; nf++) {
                asm volatile("mma.sync.aligned.m16n8k16.row.col.f32.bf16.bf16.f32 "
                             "{%0,%1,%2,%3}, {%4,%5,%6,%7}, {%8,%9}, {%0,%1,%2,%3};"
                             : "+f"(acc[nf][0]), "+f"(acc[nf][1]), "+f"(acc[nf][2]), "+f"(acc[nf][3])
                             : "r"(a0), "r"(a1), "r"(a2), "r"(a3), "r"(bhr[nf][0]), "r"(bhr[nf][1]));
            }
            if (USE_LO) {
                uint32_t blr[8][2];
#pragma unroll
                for (int p = 0; p < 4; p++) {
                    uint32_t brow = (uint32_t)(((kc*16 + b_rowadd)*72 + p*16 + b_coladd) * 2);
                    uint32_t laddr = bl_stage + brow;
                    asm volatile("ldmatrix.sync.aligned.m8n8.x4.trans.shared.b16 {%0,%1,%2,%3}, [%4];"
                                 : "=r"(blr[2*p][0]), "=r"(blr[2*p][1]),
                                   "=r"(blr[2*p+1][0]), "=r"(blr[2*p+1][1]) : "r"(laddr));
                }
#pragma unroll
                for (int nf = 0; nf < 8; nf++) {
                    asm volatile("mma.sync.aligned.m16n8k16.row.col.f32.bf16.bf16.f32 "
                                 "{%0,%1,%2,%3}, {%4,%5,%6,%7}, {%8,%9}, {%0,%1,%2,%3};"
                                 : "+f"(acc[nf][0]), "+f"(acc[nf][1]), "+f"(acc[nf][2]), "+f"(acc[nf][3])
                                 : "r"(a0), "r"(a1), "r"(a2), "r"(a3), "r"(blr[nf][0]), "r"(blr[nf][1]));
                }
            }
        }
        __syncthreads();
    }

    // ---------------- epilogue ----------------
    size_t rbase = (size_t)bh * S_LEN * HDIM;
    int row0 = m0 + wid*16 + (lane >> 2);
    int colb = (lane & 3) * 2;

    if (epi == 0) {
        float lam = softplusf(lambda_reg[0]) + F_EPS;
#pragma unroll
        for (int hh = 0; hh < 2; hh++) {
            int row = row0 + hh*8;
#pragma unroll
            for (int nf = 0; nf < 8; nf++) {
                size_t off = rbase + (size_t)row * HDIM + nf*8 + colb;
                float2 v2 = *(const float2*)&g_v[off];
                float2 a2 = *(const float2*)&g_alpha[off];
                float2 r;
                r.x = v2.x - acc[nf][hh*2+0] - lam * a2.x;
                r.y = v2.y - acc[nf][hh*2+1] - lam * a2.y;
                *(float2*)&g_resid[off] = r;
            }
        }
    } else if (epi == 2) {
#pragma unroll
        for (int hh = 0; hh < 2; hh++) {
            int row = row0 + hh*8;
#pragma unroll
            for (int nf = 0; nf < 8; nf++) {
                size_t off = rbase + (size_t)row * HDIM + nf*8 + colb;
                *(float2*)&g_resid[off] = make_float2(acc[nf][hh*2+0], acc[nf][hh*2+1]);
            }
        }
    } else {  // epi == 3: acc += partial; XSA subtract; write ctx
        float xsa = xsa_scale[0];
        int b = bh >> 4, h = bh & 15;
#pragma unroll
        for (int hh = 0; hh < 2; hh++) {
            int row = row0 + hh*8;
            float o[8][2], vv[8][2];
            float pov = 0.f, pvv = 0.f;
#pragma unroll
            for (int nf = 0; nf < 8; nf++) {
                size_t off = rbase + (size_t)row * HDIM + nf*8 + colb;
                float2 p2 = *(const float2*)&g_resid[off];
                float2 v2 = *(const float2*)&g_v[off];
                o[nf][0] = acc[nf][hh*2+0] + p2.x;
                o[nf][1] = acc[nf][hh*2+1] + p2.y;
                vv[nf][0] = v2.x; vv[nf][1] = v2.y;
                pov += o[nf][0]*v2.x + o[nf][1]*v2.y;
                pvv += v2.x*v2.x + v2.y*v2.y;
            }
            pov += __shfl_xor_sync(0xffffffffu, pov, 1);
            pvv += __shfl_xor_sync(0xffffffffu, pvv, 1);
            pov += __shfl_xor_sync(0xffffffffu, pov, 2);
            pvv += __shfl_xor_sync(0xffffffffu, pvv, 2);
            float c = xsa * pov / (pvv + F_EPS);
#pragma unroll
            for (int nf = 0; nf < 8; nf++) {
                float2 w;
                w.x = o[nf][0] - c * vv[nf][0];
                w.y = o[nf][1] - c * vv[nf][1];
                *(float2*)&g_ctx[((size_t)b * S_LEN + row) * DM + h * HDIM + nf*8 + colb] = w;
            }
        }
    }
#undef LOAD_STAGE
}

// ---------------- ltr partials ----------------
__global__ __launch_bounds__(256) void ltr_kernel(const float* __restrict__ resid) {
    __shared__ float Rs[64][64];
    __shared__ float Ls[64][16];
    int tid = threadIdx.x;
    int bh = blockIdx.x, chunk = blockIdx.y;
    int h = bh & 15;
    int s0 = chunk * 256;
    int d = tid & 63;
    int rb = (tid >> 6) * 4;
    float acc[4] = {0.f, 0.f, 0.f, 0.f};
    size_t rbase = (size_t)bh * S_LEN * HDIM;
    for (int c = 0; c < 4; c++) {
        int sb = s0 + c * 64;
#pragma unroll
        for (int i = 0; i < 4; i++) {
            int f4 = tid + i * 256;
            int row = f4 >> 4, c4 = (f4 & 15) * 4;
            *(float4*)&Rs[row][c4] = *(const float4*)&resid[rbase + (size_t)(sb + row) * HDIM + c4];
        }
        {
            int row = tid >> 2, c4 = (tid & 3) * 4;
            *(float4*)&Ls[row][c4] = *(const float4*)&g_lr[((size_t)h * S_LEN + sb + row) * RK + c4];
        }
        __syncthreads();
#pragma unroll 8
        for (int s = 0; s < 64; s++) {
            float rv = Rs[s][d];
#pragma unroll
            for (int j = 0; j < 4; j++) acc[j] = fmaf(Ls[s][rb + j], rv, acc[j]);
        }
        __syncthreads();
    }
#pragma unroll
    for (int j = 0; j < 4; j++)
        g_ltr[(((size_t)bh * 8 + chunk) * RK + rb + j) * HDIM + d] = acc[j];
}

// ---------------- alpha update; also emit bf16 hi/lo of alpha ----------------
__global__ __launch_bounds__(256) void update_kernel(
    const float* __restrict__ resid, int first,
    const float* __restrict__ diag_scale, const float* __restrict__ reg)
{
    __shared__ float Lt[16][64];
    __shared__ float Ls[64][16];
    int tid = threadIdx.x;
    int bh = blockIdx.x;
    int h = bh & 15;
    int s0 = blockIdx.y * 64;
#pragma unroll
    for (int i = 0; i < 4; i++) {
        int e = tid + i * 256;
        int r = e >> 6, d2 = e & 63;
        float s = 0.f;
#pragma unroll
        for (int p = 0; p < 8; p++) s += g_ltr[(((size_t)bh * 8 + p) * RK + r) * HDIM + d2];
        Lt[r][d2] = s;
    }
    {
        int row = tid >> 2, c4 = (tid & 3) * 4;
        *(float4*)&Ls[row][c4] = *(const float4*)&g_lr[((size_t)h * S_LEN + s0 + row) * RK + c4];
    }
    __syncthreads();
    float dp = 0.6931471805599453f * diag_scale[h] + reg[0];
    int d = tid & 63;
    int sb = (tid >> 6) * 16;
    size_t rbase = (size_t)bh * S_LEN * HDIM;
#pragma unroll 4
    for (int ii = 0; ii < 16; ii++) {
        int sl = sb + ii;
        size_t off = rbase + (size_t)(s0 + sl) * HDIM + d;
        float r = resid[off];
        float pre = r * dp;
#pragma unroll
        for (int rr = 0; rr < 16; rr++) pre = fmaf(Ls[sl][rr], Lt[rr][d], pre);
        float aold = first ? 0.f : g_alpha[off];
        float an = fminf(fmaxf(aold + pre, -CLIPA), CLIPA);
        g_alpha[off] = an;
        __nv_bfloat16 hi = __float2bfloat16_rn(an);
        g_ahi[off] = hi;
        g_alo[off] = __float2bfloat16_rn(an - __bfloat162float(hi));
    }
}

// ---------------- host ----------------
extern "C" void kernel_launch(void* const* d_in, const int* in_sizes, int n_in,
                              void* d_out, int out_size)
{
    (void)in_sizes; (void)n_in; (void)out_size;
    const float* x     = (const float*)d_in[0];
    const float* w_q   = (const float*)d_in[1];
    const float* w_k   = (const float*)d_in[2];
    const float* w_v   = (const float*)d_in[3];
    const float* w_o   = (const float*)d_in[4];
    const float* bandw = (const float*)d_in[5];
    const float* dscal = (const float*)d_in[6];
    const float* pos   = (const float*)d_in[7];
    const float* hproj = (const float*)d_in[8];
    const float* reg   = (const float*)d_in[9];
    const float* lamr  = (const float*)d_in[10];
    const float* xsa   = (const float*)d_in[11];

    float *p_q, *p_k, *p_v, *p_alpha, *p_resid, *p_ctx;
    __nv_bfloat16 *p_kh, *p_kl;
    cudaGetSymbolAddress((void**)&p_q,     g_q);
    cudaGetSymbolAddress((void**)&p_k,     g_k);
    cudaGetSymbolAddress((void**)&p_v,     g_v);
    cudaGetSymbolAddress((void**)&p_alpha, g_alpha);
    cudaGetSymbolAddress((void**)&p_resid, g_resid);
    cudaGetSymbolAddress((void**)&p_ctx,   g_ctx);
    cudaGetSymbolAddress((void**)&p_kh,    g_kh);
    cudaGetSymbolAddress((void**)&p_kl,    g_kl);

    static int smem_set = 0;
    if (!smem_set) {
        cudaFuncSetAttribute(solve_mma_kernel<false>,
                             cudaFuncAttributeMaxDynamicSharedMemorySize, SOLVE_SMEM_HI);
        cudaFuncSetAttribute(solve_mma_kernel<true>,
                             cudaFuncAttributeMaxDynamicSharedMemorySize, SOLVE_SMEM_LO);
        smem_set = 1;
    }

    dim3 blk(256);
    dim3 gProj(DM / 128, (BSZ * S_LEN) / 128);

    gemm_nt_kernel<<<gProj, blk>>>(x, w_q, p_q, BSZ * S_LEN, DM, DM, 1);
    gemm_nt_kernel<<<gProj, blk>>>(x, w_k, p_k, BSZ * S_LEN, DM, DM, 1);
    gemm_nt_kernel<<<gProj, blk>>>(x, w_v, p_v, BSZ * S_LEN, DM, DM, 1);

    rowsq_kernel<<<16384, 256>>>();
    build_kernel<<<dim3(32, 16, 32), blk>>>(bandw);
    lr_kernel<<<(NH * S_LEN) / 256, 256>>>(pos, hproj);

    for (int it = 0; it < 8; it++) {
        const float* resid = (it == 0) ? p_v : p_resid;
        if (it > 0)   // residual: K_hi @ alpha_hi only (lo term ~4e-8 abs, negligible)
            solve_mma_kernel<false><<<dim3(16, 32), blk, SOLVE_SMEM_HI>>>(p_kh, 0, lamr, xsa);
        ltr_kernel<<<dim3(32, 8), blk>>>(resid);
        update_kernel<<<dim3(32, 32), blk>>>(resid, it == 0 ? 1 : 0, dscal, reg);
    }

    // Final: out = K_hi@(a_hi+a_lo) + K_lo@a_hi  (K_lo@a_lo ~4e-6 rel, dropped)
    solve_mma_kernel<true ><<<dim3(16, 32), blk, SOLVE_SMEM_LO>>>(p_kh, 2, lamr, xsa);
    solve_mma_kernel<false><<<dim3(16, 32), blk, SOLVE_SMEM_HI>>>(p_kl, 3, lamr, xsa);

    gemm_nt_kernel<<<gProj, blk>>>(p_ctx, w_o, (float*)d_out, BSZ * S_LEN, DM, DM, 0);
}